// round 5
// baseline (speedup 1.0000x reference)
#include <cuda_runtime.h>
#include <cuda_fp16.h>
#include <cstdint>

// Problem constants
#define Dc     256
#define Kc     1024
#define HWc    1024
#define NTOK   65536
#define NELEM  16777216

#define NBLK   512          // token blocks of 128
#define M_TILE 128
#define NCHUNK 8            // 1024 / 128 codes per chunk
#define NSTG   8            // 8 k-stages of 32 per 256-d
#define TSTAGE 64           // flat stages = NCHUNK * NSTG
#define NTHR   512          // 16 warps

// gA: [512 bm][2 plane][8 stage][128 rows][64B]  (fp16, linear)  = 64 MB
// gB: [8 nc][2 plane][8 stage][128 rows][64B]                     = 1 MB
__device__ __align__(128) unsigned char gA[(size_t)NBLK * 131072];
__device__ __align__(128) unsigned char gB[8 * 2 * 8 * 8192];
__device__ float g_cnorm[Kc];
__device__ int   g_idx[NTOK];

// dynamic smem layout (argmin kernel)
#define SM_A     0          // 16 tiles x 8192 = 128KB  ([plane][stage])
#define SM_B     131072     // ring: 4 bufs x 16KB (hi 8KB + lo 8KB) = 64KB
#define SM_CN    196608     // 4KB
#define SM_BEST  200704     // 1KB
#define SM_TOTAL 201728

__device__ __forceinline__ uint32_t smem_u32(const void* p) {
    uint32_t a;
    asm("{ .reg .u64 t; cvta.to.shared.u64 t, %1; cvt.u32.u64 %0, t; }" : "=r"(a) : "l"(p));
    return a;
}
__device__ __forceinline__ void cp16(uint32_t dst, const void* src) {
    asm volatile("cp.async.cg.shared.global [%0], [%1], 16;" :: "r"(dst), "l"(src) : "memory");
}
__device__ __forceinline__ void cp_commit() {
    asm volatile("cp.async.commit_group;" ::: "memory");
}
__device__ __forceinline__ void cp_wait2() { asm volatile("cp.async.wait_group 2;" ::: "memory"); }
__device__ __forceinline__ void cp_wait1() { asm volatile("cp.async.wait_group 1;" ::: "memory"); }
__device__ __forceinline__ void cp_wait0() { asm volatile("cp.async.wait_group 0;" ::: "memory"); }

__device__ __forceinline__ void ldsm4(uint32_t& r0, uint32_t& r1, uint32_t& r2, uint32_t& r3,
                                      uint32_t addr) {
    asm volatile("ldmatrix.sync.aligned.m8n8.x4.shared.b16 {%0,%1,%2,%3}, [%4];"
                 : "=r"(r0), "=r"(r1), "=r"(r2), "=r"(r3) : "r"(addr));
}
__device__ __forceinline__ void mma16816(float& c0, float& c1, float& c2, float& c3,
                                         uint32_t a0, uint32_t a1, uint32_t a2, uint32_t a3,
                                         uint32_t b0, uint32_t b1) {
    asm volatile("mma.sync.aligned.m16n8k16.row.col.f32.f16.f16.f32 "
                 "{%0,%1,%2,%3}, {%4,%5,%6,%7}, {%8,%9}, {%0,%1,%2,%3};"
                 : "+f"(c0), "+f"(c1), "+f"(c2), "+f"(c3)
                 : "r"(a0), "r"(a1), "r"(a2), "r"(a3), "r"(b0), "r"(b1));
}
__device__ __forceinline__ unsigned int fkey(float f) {
    unsigned int u = __float_as_uint(f);
    return (u & 0x80000000u) ? ~u : (u | 0x80000000u);
}
__device__ __forceinline__ uint32_t pkh(float a, float b) {
    __half h0 = __float2half_rn(a), h1 = __float2half_rn(b);
    return (uint32_t)__half_as_ushort(h0) | ((uint32_t)__half_as_ushort(h1) << 16);
}

// ---------------------------------------------------------------------------
// prep A: x (b,d,hw) -> token-major fp16 hi/lo planes, stage-blocked linear.
// ---------------------------------------------------------------------------
__global__ __launch_bounds__(256) void prep_a(const float* __restrict__ x) {
    __shared__ float xs[32][132];
    const int bm = blockIdx.x, stage = blockIdx.y;
    const int b = bm >> 3, hw0 = (bm & 7) << 7, d0 = stage << 5;
    const float* xb = x + ((size_t)b * Dc + d0) * HWc + hw0;

    for (int i = threadIdx.x; i < 1024; i += 256) {
        int d = i >> 5, q = i & 31;
        float4 v = *reinterpret_cast<const float4*>(xb + (size_t)d * HWc + q * 4);
        xs[d][4*q] = v.x; xs[d][4*q+1] = v.y; xs[d][4*q+2] = v.z; xs[d][4*q+3] = v.w;
    }
    __syncthreads();

    unsigned char* outHi = gA + (size_t)bm * 131072 + (size_t)stage * 8192;
    unsigned char* outLo = outHi + 8 * 8192;
    #pragma unroll
    for (int v = 0; v < 2; v++) {
        int id = v * 256 + threadIdx.x;
        int r = id >> 2, u = id & 3;
        uint32_t hw_[4], lw_[4];
        #pragma unroll
        for (int p = 0; p < 4; p++) {
            float v0 = xs[u*8 + 2*p][r], v1 = xs[u*8 + 2*p + 1][r];
            __half h0 = __float2half_rn(v0), h1 = __float2half_rn(v1);
            float l0 = v0 - __half2float(h0), l1 = v1 - __half2float(h1);
            hw_[p] = (uint32_t)__half_as_ushort(h0) | ((uint32_t)__half_as_ushort(h1) << 16);
            lw_[p] = pkh(l0, l1);
        }
        *reinterpret_cast<uint4*>(outHi + (size_t)id * 16) = make_uint4(hw_[0], hw_[1], hw_[2], hw_[3]);
        *reinterpret_cast<uint4*>(outLo + (size_t)id * 16) = make_uint4(lw_[0], lw_[1], lw_[2], lw_[3]);
    }
}

// ---------------------------------------------------------------------------
// prep B: codebook -> fp16 hi/lo stage-blocked linear. grid (8 nc, 8 stage)
// ---------------------------------------------------------------------------
__global__ __launch_bounds__(256) void prep_b(const float* __restrict__ cb) {
    const int nc = blockIdx.x, stage = blockIdx.y;
    unsigned char* outHi = gB + ((size_t)(nc * 2 + 0) * 8 + stage) * 8192;
    unsigned char* outLo = gB + ((size_t)(nc * 2 + 1) * 8 + stage) * 8192;
    #pragma unroll
    for (int v = 0; v < 2; v++) {
        int id = v * 256 + threadIdx.x;
        int r = id >> 2, u = id & 3;
        const float* src = cb + (size_t)(nc * 128 + r) * Dc + stage * 32 + u * 8;
        uint32_t hw_[4], lw_[4];
        #pragma unroll
        for (int p = 0; p < 4; p++) {
            float v0 = src[2*p], v1 = src[2*p + 1];
            __half h0 = __float2half_rn(v0), h1 = __float2half_rn(v1);
            float l0 = v0 - __half2float(h0), l1 = v1 - __half2float(h1);
            hw_[p] = (uint32_t)__half_as_ushort(h0) | ((uint32_t)__half_as_ushort(h1) << 16);
            lw_[p] = pkh(l0, l1);
        }
        *reinterpret_cast<uint4*>(outHi + (size_t)id * 16) = make_uint4(hw_[0], hw_[1], hw_[2], hw_[3]);
        *reinterpret_cast<uint4*>(outLo + (size_t)id * 16) = make_uint4(lw_[0], lw_[1], lw_[2], lw_[3]);
    }
}

// ---------------------------------------------------------------------------
__global__ void cnorm_kernel(const float* __restrict__ cb) {
    int warp = (blockIdx.x * blockDim.x + threadIdx.x) >> 5;
    int lane = threadIdx.x & 31;
    if (warp >= Kc) return;
    const float* row = cb + warp * Dc;
    float s = 0.f;
    #pragma unroll
    for (int d = lane; d < Dc; d += 32) { float v = row[d]; s = fmaf(v, v, s); }
    #pragma unroll
    for (int o = 16; o; o >>= 1) s += __shfl_xor_sync(0xFFFFFFFFu, s, o);
    if (lane == 0) g_cnorm[warp] = s;
}

// ---------------------------------------------------------------------------
// argmin via mma.sync: 16 warps (4x4 warp grid, 32x32 warp tiles), merged
// 3-pass stages. Flat loop over 64 k-stages; B via 4-deep cp.async ring.
// ---------------------------------------------------------------------------
__global__ __launch_bounds__(NTHR, 1) void argmin_mma() {
    extern __shared__ __align__(128) unsigned char smem[];
    const uint32_t sb = smem_u32(smem);
    const int tid = threadIdx.x, lane = tid & 31, wid = tid >> 5;
    const int wm = wid & 3, wn = wid >> 2;
    const int bm = blockIdx.x;

    float* sm_cn = reinterpret_cast<float*>(smem + SM_CN);
    unsigned long long* sBest = reinterpret_cast<unsigned long long*>(smem + SM_BEST);
    for (int i = tid; i < Kc; i += NTHR) sm_cn[i] = g_cnorm[i];
    if (tid < 128) sBest[tid] = ~0ull;

    // A image -> smem
    {
        const unsigned char* src = gA + (size_t)bm * 131072;
        #pragma unroll
        for (int v = 0; v < 16; v++) {
            int id = v * NTHR + tid;
            int tile = id >> 9, r = (id >> 2) & 127, u = id & 3;
            uint32_t dst = sb + SM_A + tile * 8192 + r * 64 + 16 * (u ^ ((r >> 1) & 3));
            cp16(dst, src + (size_t)id * 16);
        }
        cp_commit();
    }

    auto issueB = [&](int t) {
        int nc = t >> 3, s = t & 7;
        uint32_t buf = sb + SM_B + (t & 3) * 16384;
        const unsigned char* srcHi = gB + ((size_t)(nc * 2 + 0) * 8 + s) * 8192;
        const unsigned char* srcLo = gB + ((size_t)(nc * 2 + 1) * 8 + s) * 8192;
        int r = tid >> 2, u = tid & 3;
        uint32_t off = r * 64 + 16 * (u ^ ((r >> 1) & 3));
        cp16(buf + off, srcHi + (size_t)tid * 16);
        cp16(buf + 8192 + off, srcLo + (size_t)tid * 16);
        cp_commit();
    };

    issueB(0); issueB(1); issueB(2);

    // lane-fixed fragment address components
    const int a_r = wm * 32 + (lane & 15);                       // + mi*16
    const int a_u = lane >> 4;                                   // + kk*2
    const int b_r = wn * 32 + (lane & 7) + ((lane >> 4) << 3);   // + np*16
    const int b_u = (lane >> 3) & 1;                             // + kk*2

    float best4[4];
    int   bid4[4];
    #pragma unroll
    for (int i = 0; i < 4; i++) { best4[i] = 3.4e38f; bid4[i] = 0; }

    float acc[2][4][4];
    #pragma unroll
    for (int mi = 0; mi < 2; mi++)
        #pragma unroll
        for (int ni = 0; ni < 4; ni++)
            #pragma unroll
            for (int c = 0; c < 4; c++) acc[mi][ni][c] = 0.f;

    #pragma unroll 1
    for (int t = 0; t < TSTAGE; t++) {
        if (t <= TSTAGE - 3)      cp_wait2();
        else if (t == TSTAGE - 2) cp_wait1();
        else                      cp_wait0();
        __syncthreads();
        if (t + 3 < TSTAGE) issueB(t + 3);

        const int s = t & 7;
        const uint32_t bufhi = sb + SM_B + (t & 3) * 16384;
        const uint32_t buflo = bufhi + 8192;
        const uint32_t SAhi  = sb + SM_A + s * 8192;
        const uint32_t SAlo  = SAhi + 65536;

        #pragma unroll
        for (int kk = 0; kk < 2; kk++) {
            uint32_t bh[8], bl[8], ah[8], al[8];
            #pragma unroll
            for (int np = 0; np < 2; np++) {
                int r = b_r + np * 16;
                int c = kk * 2 + b_u;
                uint32_t off = r * 64 + 16 * (c ^ ((r >> 1) & 3));
                ldsm4(bh[np*4+0], bh[np*4+1], bh[np*4+2], bh[np*4+3], bufhi + off);
                ldsm4(bl[np*4+0], bl[np*4+1], bl[np*4+2], bl[np*4+3], buflo + off);
            }
            #pragma unroll
            for (int mi = 0; mi < 2; mi++) {
                int r = a_r + mi * 16;
                int c = kk * 2 + a_u;
                uint32_t off = r * 64 + 16 * (c ^ ((r >> 1) & 3));
                ldsm4(ah[mi*4+0], ah[mi*4+1], ah[mi*4+2], ah[mi*4+3], SAhi + off);
                ldsm4(al[mi*4+0], al[mi*4+1], al[mi*4+2], al[mi*4+3], SAlo + off);
            }
            // pass 1: A-hi * B-hi
            #pragma unroll
            for (int mi = 0; mi < 2; mi++)
                #pragma unroll
                for (int ni = 0; ni < 4; ni++)
                    mma16816(acc[mi][ni][0], acc[mi][ni][1], acc[mi][ni][2], acc[mi][ni][3],
                             ah[mi*4+0], ah[mi*4+1], ah[mi*4+2], ah[mi*4+3],
                             bh[(ni>>1)*4 + (ni&1)*2], bh[(ni>>1)*4 + (ni&1)*2 + 1]);
            // pass 2: A-lo * B-hi
            #pragma unroll
            for (int mi = 0; mi < 2; mi++)
                #pragma unroll
                for (int ni = 0; ni < 4; ni++)
                    mma16816(acc[mi][ni][0], acc[mi][ni][1], acc[mi][ni][2], acc[mi][ni][3],
                             al[mi*4+0], al[mi*4+1], al[mi*4+2], al[mi*4+3],
                             bh[(ni>>1)*4 + (ni&1)*2], bh[(ni>>1)*4 + (ni&1)*2 + 1]);
            // pass 3: A-hi * B-lo
            #pragma unroll
            for (int mi = 0; mi < 2; mi++)
                #pragma unroll
                for (int ni = 0; ni < 4; ni++)
                    mma16816(acc[mi][ni][0], acc[mi][ni][1], acc[mi][ni][2], acc[mi][ni][3],
                             ah[mi*4+0], ah[mi*4+1], ah[mi*4+2], ah[mi*4+3],
                             bl[(ni>>1)*4 + (ni&1)*2], bl[(ni>>1)*4 + (ni&1)*2 + 1]);
        }

        if (s == 7) {
            const int nc = t >> 3;
            #pragma unroll
            for (int mi = 0; mi < 2; mi++)
                #pragma unroll
                for (int ni = 0; ni < 4; ni++)
                    #pragma unroll
                    for (int c = 0; c < 4; c++) {
                        int code = nc * 128 + wn * 32 + ni * 8 + (lane & 3) * 2 + (c & 1);
                        float score = fmaf(-2.f, acc[mi][ni][c], sm_cn[code]);
                        int slot = mi * 2 + (c >> 1);
                        if (score < best4[slot]) { best4[slot] = score; bid4[slot] = code; }
                        acc[mi][ni][c] = 0.f;
                    }
        }
    }

    __syncthreads();
    #pragma unroll
    for (int slot = 0; slot < 4; slot++) {
        int row = wm * 32 + (slot >> 1) * 16 + (lane >> 2) + 8 * (slot & 1);
        unsigned long long pack =
            ((unsigned long long)fkey(best4[slot]) << 32) | (unsigned int)bid4[slot];
        atomicMin(&sBest[row], pack);
    }
    __syncthreads();
    if (tid < 128)
        g_idx[bm * M_TILE + tid] = (int)(unsigned int)(sBest[tid] & 0xFFFFFFFFull);
}

// ---------------------------------------------------------------------------
__global__ void output_kernel(const float* __restrict__ x,
                              const float* __restrict__ cb,
                              float* __restrict__ zhat,
                              float* __restrict__ zq)
{
    int t = blockIdx.x * blockDim.x + threadIdx.x;
    if (t >= NELEM / 4) return;
    int n  = t >> 6;
    int d4 = t & 63;
    int k  = g_idx[n];
    float4 c  = *reinterpret_cast<const float4*>(cb + (size_t)k * Dc + d4 * 4);
    float4 xv = *reinterpret_cast<const float4*>(x + (size_t)t * 4);
    float4 zh;
    zh.x = xv.x + (c.x - xv.x);
    zh.y = xv.y + (c.y - xv.y);
    zh.z = xv.z + (c.z - xv.z);
    zh.w = xv.w + (c.w - xv.w);
    *reinterpret_cast<float4*>(zq   + (size_t)t * 4) = c;
    *reinterpret_cast<float4*>(zhat + (size_t)t * 4) = zh;
}

// ---------------------------------------------------------------------------
extern "C" void kernel_launch(void* const* d_in, const int* in_sizes, int n_in,
                              void* d_out, int out_size)
{
    const float* x  = (const float*)d_in[0];
    const float* cb = (const float*)d_in[1];
    float* zhat = (float*)d_out;
    float* zq   = (float*)d_out + NELEM;

    static int attr_set = 0;
    if (!attr_set) {
        cudaFuncSetAttribute(argmin_mma, cudaFuncAttributeMaxDynamicSharedMemorySize, SM_TOTAL);
        attr_set = 1;
    }

    prep_a<<<dim3(NBLK, NSTG), 256>>>(x);
    prep_b<<<dim3(8, NSTG), 256>>>(cb);
    cnorm_kernel<<<Kc / 8, 256>>>(cb);
    argmin_mma<<<NBLK, NTHR, SM_TOTAL>>>();
    output_kernel<<<(NELEM / 4 + 255) / 256, 256>>>(x, cb, zhat, zq);
}

// round 6
// speedup vs baseline: 1.0532x; 1.0532x over previous
#include <cuda_runtime.h>
#include <cuda_fp16.h>
#include <cstdint>

// Problem constants
#define Dc     256
#define Kc     1024
#define HWc    1024
#define NTOK   65536
#define NELEM  16777216

#define NBLK   512          // token blocks of 128
#define M_TILE 128
#define NCHUNK 8            // 1024 / 128 codes per chunk
#define NSTG   8            // 8 k-stages of 32 per 256-d
#define TSTAGE 64           // flat stages = NCHUNK * NSTG
#define NTHR   256          // 8 warps, 2x4 warp grid, 64x32 warp tiles

// gA: [512 bm][2 plane][8 stage][128 rows][64B]  (fp16, linear)  = 64 MB
// gB: [8 nc][2 plane][8 stage][128 rows][64B]                     = 1 MB
__device__ __align__(128) unsigned char gA[(size_t)NBLK * 131072];
__device__ __align__(128) unsigned char gB[8 * 2 * 8 * 8192];
__device__ float g_cnorm[Kc];
__device__ int   g_idx[NTOK];

// dynamic smem layout (argmin kernel)
#define SM_A     0          // 16 tiles x 8192 = 128KB  ([plane][stage])
#define SM_B     131072     // ring: 4 bufs x 16KB (hi 8KB + lo 8KB) = 64KB
#define SM_CN    196608     // 4KB
#define SM_BEST  200704     // 1KB
#define SM_TOTAL 201728

__device__ __forceinline__ uint32_t smem_u32(const void* p) {
    uint32_t a;
    asm("{ .reg .u64 t; cvta.to.shared.u64 t, %1; cvt.u32.u64 %0, t; }" : "=r"(a) : "l"(p));
    return a;
}
__device__ __forceinline__ void cp16(uint32_t dst, const void* src) {
    asm volatile("cp.async.cg.shared.global [%0], [%1], 16;" :: "r"(dst), "l"(src) : "memory");
}
__device__ __forceinline__ void cp_commit() {
    asm volatile("cp.async.commit_group;" ::: "memory");
}
__device__ __forceinline__ void cp_wait3() { asm volatile("cp.async.wait_group 3;" ::: "memory"); }
__device__ __forceinline__ void cp_wait2() { asm volatile("cp.async.wait_group 2;" ::: "memory"); }
__device__ __forceinline__ void cp_wait1() { asm volatile("cp.async.wait_group 1;" ::: "memory"); }
__device__ __forceinline__ void cp_wait0() { asm volatile("cp.async.wait_group 0;" ::: "memory"); }

__device__ __forceinline__ void ldsm4(uint32_t& r0, uint32_t& r1, uint32_t& r2, uint32_t& r3,
                                      uint32_t addr) {
    asm volatile("ldmatrix.sync.aligned.m8n8.x4.shared.b16 {%0,%1,%2,%3}, [%4];"
                 : "=r"(r0), "=r"(r1), "=r"(r2), "=r"(r3) : "r"(addr));
}
__device__ __forceinline__ void mma16816(float& c0, float& c1, float& c2, float& c3,
                                         uint32_t a0, uint32_t a1, uint32_t a2, uint32_t a3,
                                         uint32_t b0, uint32_t b1) {
    asm volatile("mma.sync.aligned.m16n8k16.row.col.f32.f16.f16.f32 "
                 "{%0,%1,%2,%3}, {%4,%5,%6,%7}, {%8,%9}, {%0,%1,%2,%3};"
                 : "+f"(c0), "+f"(c1), "+f"(c2), "+f"(c3)
                 : "r"(a0), "r"(a1), "r"(a2), "r"(a3), "r"(b0), "r"(b1));
}
__device__ __forceinline__ unsigned int fkey(float f) {
    unsigned int u = __float_as_uint(f);
    return (u & 0x80000000u) ? ~u : (u | 0x80000000u);
}
__device__ __forceinline__ uint32_t pkh(float a, float b) {
    __half h0 = __float2half_rn(a), h1 = __float2half_rn(b);
    return (uint32_t)__half_as_ushort(h0) | ((uint32_t)__half_as_ushort(h1) << 16);
}

// ---------------------------------------------------------------------------
// prep A: x (b,d,hw) -> token-major fp16 hi/lo planes, stage-blocked linear.
// ---------------------------------------------------------------------------
__global__ __launch_bounds__(256) void prep_a(const float* __restrict__ x) {
    __shared__ float xs[32][132];
    const int bm = blockIdx.x, stage = blockIdx.y;
    const int b = bm >> 3, hw0 = (bm & 7) << 7, d0 = stage << 5;
    const float* xb = x + ((size_t)b * Dc + d0) * HWc + hw0;

    for (int i = threadIdx.x; i < 1024; i += 256) {
        int d = i >> 5, q = i & 31;
        float4 v = *reinterpret_cast<const float4*>(xb + (size_t)d * HWc + q * 4);
        xs[d][4*q] = v.x; xs[d][4*q+1] = v.y; xs[d][4*q+2] = v.z; xs[d][4*q+3] = v.w;
    }
    __syncthreads();

    unsigned char* outHi = gA + (size_t)bm * 131072 + (size_t)stage * 8192;
    unsigned char* outLo = outHi + 8 * 8192;
    #pragma unroll
    for (int v = 0; v < 2; v++) {
        int id = v * 256 + threadIdx.x;
        int r = id >> 2, u = id & 3;
        uint32_t hw_[4], lw_[4];
        #pragma unroll
        for (int p = 0; p < 4; p++) {
            float v0 = xs[u*8 + 2*p][r], v1 = xs[u*8 + 2*p + 1][r];
            __half h0 = __float2half_rn(v0), h1 = __float2half_rn(v1);
            float l0 = v0 - __half2float(h0), l1 = v1 - __half2float(h1);
            hw_[p] = (uint32_t)__half_as_ushort(h0) | ((uint32_t)__half_as_ushort(h1) << 16);
            lw_[p] = pkh(l0, l1);
        }
        *reinterpret_cast<uint4*>(outHi + (size_t)id * 16) = make_uint4(hw_[0], hw_[1], hw_[2], hw_[3]);
        *reinterpret_cast<uint4*>(outLo + (size_t)id * 16) = make_uint4(lw_[0], lw_[1], lw_[2], lw_[3]);
    }
}

// ---------------------------------------------------------------------------
// prep B: codebook -> fp16 hi/lo stage-blocked linear. grid (8 nc, 8 stage)
// ---------------------------------------------------------------------------
__global__ __launch_bounds__(256) void prep_b(const float* __restrict__ cb) {
    const int nc = blockIdx.x, stage = blockIdx.y;
    unsigned char* outHi = gB + ((size_t)(nc * 2 + 0) * 8 + stage) * 8192;
    unsigned char* outLo = gB + ((size_t)(nc * 2 + 1) * 8 + stage) * 8192;
    #pragma unroll
    for (int v = 0; v < 2; v++) {
        int id = v * 256 + threadIdx.x;
        int r = id >> 2, u = id & 3;
        const float* src = cb + (size_t)(nc * 128 + r) * Dc + stage * 32 + u * 8;
        uint32_t hw_[4], lw_[4];
        #pragma unroll
        for (int p = 0; p < 4; p++) {
            float v0 = src[2*p], v1 = src[2*p + 1];
            __half h0 = __float2half_rn(v0), h1 = __float2half_rn(v1);
            float l0 = v0 - __half2float(h0), l1 = v1 - __half2float(h1);
            hw_[p] = (uint32_t)__half_as_ushort(h0) | ((uint32_t)__half_as_ushort(h1) << 16);
            lw_[p] = pkh(l0, l1);
        }
        *reinterpret_cast<uint4*>(outHi + (size_t)id * 16) = make_uint4(hw_[0], hw_[1], hw_[2], hw_[3]);
        *reinterpret_cast<uint4*>(outLo + (size_t)id * 16) = make_uint4(lw_[0], lw_[1], lw_[2], lw_[3]);
    }
}

// ---------------------------------------------------------------------------
__global__ void cnorm_kernel(const float* __restrict__ cb) {
    int warp = (blockIdx.x * blockDim.x + threadIdx.x) >> 5;
    int lane = threadIdx.x & 31;
    if (warp >= Kc) return;
    const float* row = cb + warp * Dc;
    float s = 0.f;
    #pragma unroll
    for (int d = lane; d < Dc; d += 32) { float v = row[d]; s = fmaf(v, v, s); }
    #pragma unroll
    for (int o = 16; o; o >>= 1) s += __shfl_xor_sync(0xFFFFFFFFu, s, o);
    if (lane == 0) g_cnorm[warp] = s;
}

// ---------------------------------------------------------------------------
// argmin via mma.sync, 8 warps (2x4 grid, 64x32 warp tiles), merged 3-pass
// stages, register-level fragment pipelining: A kk0 fragments prefetched
// across the stage barrier; B kk1 / A kk1 / next-A loads interleaved between
// MMA groups so crossbar traffic hides under tensor execution.
// ---------------------------------------------------------------------------
__global__ __launch_bounds__(NTHR, 1) void argmin_mma() {
    extern __shared__ __align__(128) unsigned char smem[];
    const uint32_t sb = smem_u32(smem);
    const int tid = threadIdx.x, lane = tid & 31, wid = tid >> 5;
    const int wm = wid & 1, wn = wid >> 1;
    const int bm = blockIdx.x;

    float* sm_cn = reinterpret_cast<float*>(smem + SM_CN);
    unsigned long long* sBest = reinterpret_cast<unsigned long long*>(smem + SM_BEST);
    for (int i = tid; i < Kc; i += NTHR) sm_cn[i] = g_cnorm[i];
    if (tid < 128) sBest[tid] = ~0ull;

    // A image -> smem (group 0)
    {
        const unsigned char* src = gA + (size_t)bm * 131072;
        #pragma unroll
        for (int v = 0; v < 32; v++) {
            int id = v * NTHR + tid;
            int tile = id >> 9, r = (id >> 2) & 127, u = id & 3;
            uint32_t dst = sb + SM_A + tile * 8192 + r * 64 + 16 * (u ^ ((r >> 1) & 3));
            cp16(dst, src + (size_t)id * 16);
        }
        cp_commit();
    }

    auto issueB = [&](int t) {
        int nc = t >> 3, s = t & 7;
        uint32_t buf = sb + SM_B + (t & 3) * 16384;
        const unsigned char* srcHi = gB + ((size_t)(nc * 2 + 0) * 8 + s) * 8192;
        const unsigned char* srcLo = gB + ((size_t)(nc * 2 + 1) * 8 + s) * 8192;
        #pragma unroll
        for (int v = 0; v < 2; v++) {
            int id = v * NTHR + tid;
            int r = id >> 2, u = id & 3;
            uint32_t off = r * 64 + 16 * (u ^ ((r >> 1) & 3));
            cp16(buf + off, srcHi + (size_t)id * 16);
            cp16(buf + 8192 + off, srcLo + (size_t)id * 16);
        }
        cp_commit();
    };

    issueB(0); issueB(1); issueB(2);   // groups 1..3

    // lane-fixed fragment address components
    const int a_r = wm * 64 + (lane & 15);                       // + mi*16
    const int a_u = lane >> 4;                                   // + kk*2
    const int b_r = wn * 32 + (lane & 7) + ((lane >> 4) << 3);   // + np*16
    const int b_u = (lane >> 3) & 1;                             // + kk*2

    float best8[8];
    int   bid8[8];
    #pragma unroll
    for (int i = 0; i < 8; i++) { best8[i] = 3.4e38f; bid8[i] = 0; }

    float acc[4][4][4];
    #pragma unroll
    for (int mi = 0; mi < 4; mi++)
        #pragma unroll
        for (int ni = 0; ni < 4; ni++)
            #pragma unroll
            for (int c = 0; c < 4; c++) acc[mi][ni][c] = 0.f;

    uint32_t ah0[16], al0[16], ah1[16], al1[16];

    // A-fragment load for (stage s, kk) into (h, l)
    auto loadA = [&](uint32_t* h, uint32_t* l, int s, int kk) {
        const uint32_t SAhi = sb + SM_A + s * 8192;
        const uint32_t SAlo = SAhi + 65536;
        #pragma unroll
        for (int mi = 0; mi < 4; mi++) {
            int r = a_r + mi * 16;
            int c = kk * 2 + a_u;
            uint32_t off = r * 64 + 16 * (c ^ ((r >> 1) & 3));
            ldsm4(h[mi*4+0], h[mi*4+1], h[mi*4+2], h[mi*4+3], SAhi + off);
            ldsm4(l[mi*4+0], l[mi*4+1], l[mi*4+2], l[mi*4+3], SAlo + off);
        }
    };
    auto loadB = [&](uint32_t* h, uint32_t* l, uint32_t bufhi, int kk) {
        const uint32_t buflo = bufhi + 8192;
        #pragma unroll
        for (int np = 0; np < 2; np++) {
            int r = b_r + np * 16;
            int c = kk * 2 + b_u;
            uint32_t off = r * 64 + 16 * (c ^ ((r >> 1) & 3));
            ldsm4(h[np*4+0], h[np*4+1], h[np*4+2], h[np*4+3], bufhi + off);
            ldsm4(l[np*4+0], l[np*4+1], l[np*4+2], l[np*4+3], buflo + off);
        }
    };
    // one 3-pass MMA group (48 MMAs) for a (A,B) fragment set
    auto mmaGroup = [&](const uint32_t* ah, const uint32_t* al,
                        const uint32_t* bh, const uint32_t* bl) {
        #pragma unroll
        for (int mi = 0; mi < 4; mi++)
            #pragma unroll
            for (int ni = 0; ni < 4; ni++)
                mma16816(acc[mi][ni][0], acc[mi][ni][1], acc[mi][ni][2], acc[mi][ni][3],
                         ah[mi*4+0], ah[mi*4+1], ah[mi*4+2], ah[mi*4+3],
                         bh[(ni>>1)*4 + (ni&1)*2], bh[(ni>>1)*4 + (ni&1)*2 + 1]);
        #pragma unroll
        for (int mi = 0; mi < 4; mi++)
            #pragma unroll
            for (int ni = 0; ni < 4; ni++)
                mma16816(acc[mi][ni][0], acc[mi][ni][1], acc[mi][ni][2], acc[mi][ni][3],
                         al[mi*4+0], al[mi*4+1], al[mi*4+2], al[mi*4+3],
                         bh[(ni>>1)*4 + (ni&1)*2], bh[(ni>>1)*4 + (ni&1)*2 + 1]);
        #pragma unroll
        for (int mi = 0; mi < 4; mi++)
            #pragma unroll
            for (int ni = 0; ni < 4; ni++)
                mma16816(acc[mi][ni][0], acc[mi][ni][1], acc[mi][ni][2], acc[mi][ni][3],
                         ah[mi*4+0], ah[mi*4+1], ah[mi*4+2], ah[mi*4+3],
                         bl[(ni>>1)*4 + (ni&1)*2], bl[(ni>>1)*4 + (ni&1)*2 + 1]);
    };

    // prologue: wait for A image, preload A frags for stage 0, kk 0
    cp_wait3();
    __syncthreads();
    loadA(ah0, al0, 0, 0);

    #pragma unroll 1
    for (int t = 0; t < TSTAGE; t++) {
        if (t <= TSTAGE - 3)      cp_wait2();
        else if (t == TSTAGE - 2) cp_wait1();
        else                      cp_wait0();
        __syncthreads();
        if (t + 3 < TSTAGE) issueB(t + 3);

        const int s = t & 7;
        const uint32_t bufhi = sb + SM_B + (t & 3) * 16384;

        uint32_t bh0[8], bl0[8], bh1[8], bl1[8];
        loadB(bh0, bl0, bufhi, 0);            // minimal pre-MMA burst
        loadA(ah1, al1, s, 1);                // hides under kk0 MMAs
        mmaGroup(ah0, al0, bh0, bl0);         // 48 MMAs (kk0)
        loadB(bh1, bl1, bufhi, 1);            // hides under kk0/kk1 MMAs
        if (t < TSTAGE - 1)
            loadA(ah0, al0, (t + 1) & 7, 0);  // prefetch next stage kk0
        mmaGroup(ah1, al1, bh1, bl1);         // 48 MMAs (kk1)

        if (s == 7) {
            const int nc = t >> 3;
            #pragma unroll
            for (int mi = 0; mi < 4; mi++)
                #pragma unroll
                for (int ni = 0; ni < 4; ni++)
                    #pragma unroll
                    for (int c = 0; c < 4; c++) {
                        int code = nc * 128 + wn * 32 + ni * 8 + (lane & 3) * 2 + (c & 1);
                        float score = fmaf(-2.f, acc[mi][ni][c], sm_cn[code]);
                        int slot = mi * 2 + (c >> 1);
                        if (score < best8[slot]) { best8[slot] = score; bid8[slot] = code; }
                        acc[mi][ni][c] = 0.f;
                    }
        }
    }

    __syncthreads();
    #pragma unroll
    for (int slot = 0; slot < 8; slot++) {
        int row = wm * 64 + (slot >> 1) * 16 + (lane >> 2) + 8 * (slot & 1);
        unsigned long long pack =
            ((unsigned long long)fkey(best8[slot]) << 32) | (unsigned int)bid8[slot];
        atomicMin(&sBest[row], pack);
    }
    __syncthreads();
    if (tid < 128)
        g_idx[bm * M_TILE + tid] = (int)(unsigned int)(sBest[tid] & 0xFFFFFFFFull);
}

// ---------------------------------------------------------------------------
__global__ void output_kernel(const float* __restrict__ x,
                              const float* __restrict__ cb,
                              float* __restrict__ zhat,
                              float* __restrict__ zq)
{
    int t = blockIdx.x * blockDim.x + threadIdx.x;
    if (t >= NELEM / 4) return;
    int n  = t >> 6;
    int d4 = t & 63;
    int k  = g_idx[n];
    float4 c  = *reinterpret_cast<const float4*>(cb + (size_t)k * Dc + d4 * 4);
    float4 xv = *reinterpret_cast<const float4*>(x + (size_t)t * 4);
    float4 zh;
    zh.x = xv.x + (c.x - xv.x);
    zh.y = xv.y + (c.y - xv.y);
    zh.z = xv.z + (c.z - xv.z);
    zh.w = xv.w + (c.w - xv.w);
    *reinterpret_cast<float4*>(zq   + (size_t)t * 4) = c;
    *reinterpret_cast<float4*>(zhat + (size_t)t * 4) = zh;
}

// ---------------------------------------------------------------------------
extern "C" void kernel_launch(void* const* d_in, const int* in_sizes, int n_in,
                              void* d_out, int out_size)
{
    const float* x  = (const float*)d_in[0];
    const float* cb = (const float*)d_in[1];
    float* zhat = (float*)d_out;
    float* zq   = (float*)d_out + NELEM;

    static int attr_set = 0;
    if (!attr_set) {
        cudaFuncSetAttribute(argmin_mma, cudaFuncAttributeMaxDynamicSharedMemorySize, SM_TOTAL);
        attr_set = 1;
    }

    prep_a<<<dim3(NBLK, NSTG), 256>>>(x);
    prep_b<<<dim3(8, NSTG), 256>>>(cb);
    cnorm_kernel<<<Kc / 8, 256>>>(cb);
    argmin_mma<<<NBLK, NTHR, SM_TOTAL>>>();
    output_kernel<<<(NELEM / 4 + 255) / 256, 256>>>(x, cb, zhat, zq);
}

// round 7
// speedup vs baseline: 1.0790x; 1.0246x over previous
#include <cuda_runtime.h>
#include <cuda_fp16.h>
#include <cstdint>

// Problem constants
#define Dc     256
#define Kc     1024
#define HWc    1024
#define NTOK   65536
#define NELEM  16777216

#define NBLK   512          // token blocks of 128
#define M_TILE 128
#define NCHUNK 8            // 1024 / 128 codes per chunk
#define NSTG   8            // 8 k-stages of 32 per 256-d
#define TSTAGE 64           // flat stages = NCHUNK * NSTG
#define NTHR   288          // 8 compute warps + 1 producer warp

// PRE-SWIZZLED images (swizzle baked in by prep kernels):
// gA: [512 bm][2 plane][8 stage][8KB tile]  = 64 MB
// gB: [8 nc][2 plane][8 stage][8KB tile]    = 1 MB
__device__ __align__(128) unsigned char gA[(size_t)NBLK * 131072];
__device__ __align__(128) unsigned char gB[8 * 2 * 8 * 8192];
__device__ float g_cnorm[Kc];
__device__ int   g_idx[NTOK];

// dynamic smem layout (argmin kernel)
#define SM_A     0          // 16 tiles x 8192 = 128KB  ([plane][stage])
#define SM_B     131072     // ring: 4 bufs x 16KB (hi 8KB + lo 8KB) = 64KB
#define SM_CN    196608     // 4KB
#define SM_BEST  200704     // 1KB
#define SM_MB    201728     // mbarriers: full[4] @ +0, empty[4] @ +32
#define SM_TOTAL 201856

__device__ __forceinline__ uint32_t smem_u32(const void* p) {
    uint32_t a;
    asm("{ .reg .u64 t; cvta.to.shared.u64 t, %1; cvt.u32.u64 %0, t; }" : "=r"(a) : "l"(p));
    return a;
}
__device__ __forceinline__ void cp16(uint32_t dst, const void* src) {
    asm volatile("cp.async.cg.shared.global [%0], [%1], 16;" :: "r"(dst), "l"(src) : "memory");
}
__device__ __forceinline__ void cp_commit() {
    asm volatile("cp.async.commit_group;" ::: "memory");
}
__device__ __forceinline__ void cp_wait0() { asm volatile("cp.async.wait_group 0;" ::: "memory"); }

__device__ __forceinline__ void bulk_copy(uint32_t dst, const void* src,
                                          uint32_t bytes, uint32_t mbar) {
    asm volatile(
        "cp.async.bulk.shared::cluster.global.mbarrier::complete_tx::bytes "
        "[%0], [%1], %2, [%3];"
        :: "r"(dst), "l"(src), "r"(bytes), "r"(mbar) : "memory");
}
#define MBAR_INIT(a, c)   asm volatile("mbarrier.init.shared.b64 [%0], %1;" :: "r"(a), "r"(c) : "memory")
#define MBAR_EXPECT(a, b) asm volatile("mbarrier.arrive.expect_tx.shared.b64 _, [%0], %1;" :: "r"(a), "r"(b) : "memory")
#define MBAR_ARRIVE(a)    asm volatile("mbarrier.arrive.shared.b64 _, [%0];" :: "r"(a) : "memory")

__device__ __forceinline__ void mbar_wait(uint32_t mbar, uint32_t parity) {
    asm volatile(
        "{\n\t.reg .pred P1;\n\t"
        "WAIT_LOOP_%=:\n\t"
        "mbarrier.try_wait.parity.acquire.cta.shared::cta.b64 P1, [%0], %1, 0x989680;\n\t"
        "@P1 bra.uni WAIT_DONE_%=;\n\t"
        "bra.uni WAIT_LOOP_%=;\n\t"
        "WAIT_DONE_%=:\n\t}"
        :: "r"(mbar), "r"(parity) : "memory");
}

__device__ __forceinline__ void ldsm4(uint32_t& r0, uint32_t& r1, uint32_t& r2, uint32_t& r3,
                                      uint32_t addr) {
    asm volatile("ldmatrix.sync.aligned.m8n8.x4.shared.b16 {%0,%1,%2,%3}, [%4];"
                 : "=r"(r0), "=r"(r1), "=r"(r2), "=r"(r3) : "r"(addr));
}
__device__ __forceinline__ void mma16816(float& c0, float& c1, float& c2, float& c3,
                                         uint32_t a0, uint32_t a1, uint32_t a2, uint32_t a3,
                                         uint32_t b0, uint32_t b1) {
    asm volatile("mma.sync.aligned.m16n8k16.row.col.f32.f16.f16.f32 "
                 "{%0,%1,%2,%3}, {%4,%5,%6,%7}, {%8,%9}, {%0,%1,%2,%3};"
                 : "+f"(c0), "+f"(c1), "+f"(c2), "+f"(c3)
                 : "r"(a0), "r"(a1), "r"(a2), "r"(a3), "r"(b0), "r"(b1));
}
__device__ __forceinline__ unsigned int fkey(float f) {
    unsigned int u = __float_as_uint(f);
    return (u & 0x80000000u) ? ~u : (u | 0x80000000u);
}
__device__ __forceinline__ uint32_t pkh(float a, float b) {
    __half h0 = __float2half_rn(a), h1 = __float2half_rn(b);
    return (uint32_t)__half_as_ushort(h0) | ((uint32_t)__half_as_ushort(h1) << 16);
}
// swizzled offset within an 8KB tile for 16B unit (r, u): r*64 + 16*(u^((r>>1)&3))
__device__ __forceinline__ uint32_t swoff(int r, int u) {
    return (uint32_t)(r * 64 + 16 * (u ^ ((r >> 1) & 3)));
}

// ---------------------------------------------------------------------------
// prep A: x (b,d,hw) -> token-major fp16 hi/lo planes, PRE-SWIZZLED tiles.
// ---------------------------------------------------------------------------
__global__ __launch_bounds__(256) void prep_a(const float* __restrict__ x) {
    __shared__ float xs[32][132];
    const int bm = blockIdx.x, stage = blockIdx.y;
    const int b = bm >> 3, hw0 = (bm & 7) << 7, d0 = stage << 5;
    const float* xb = x + ((size_t)b * Dc + d0) * HWc + hw0;

    for (int i = threadIdx.x; i < 1024; i += 256) {
        int d = i >> 5, q = i & 31;
        float4 v = *reinterpret_cast<const float4*>(xb + (size_t)d * HWc + q * 4);
        xs[d][4*q] = v.x; xs[d][4*q+1] = v.y; xs[d][4*q+2] = v.z; xs[d][4*q+3] = v.w;
    }
    __syncthreads();

    unsigned char* outHi = gA + (size_t)bm * 131072 + (size_t)stage * 8192;
    unsigned char* outLo = outHi + 8 * 8192;
    #pragma unroll
    for (int v = 0; v < 2; v++) {
        int id = v * 256 + threadIdx.x;
        int r = id >> 2, u = id & 3;
        uint32_t hw_[4], lw_[4];
        #pragma unroll
        for (int p = 0; p < 4; p++) {
            float v0 = xs[u*8 + 2*p][r], v1 = xs[u*8 + 2*p + 1][r];
            __half h0 = __float2half_rn(v0), h1 = __float2half_rn(v1);
            float l0 = v0 - __half2float(h0), l1 = v1 - __half2float(h1);
            hw_[p] = (uint32_t)__half_as_ushort(h0) | ((uint32_t)__half_as_ushort(h1) << 16);
            lw_[p] = pkh(l0, l1);
        }
        uint32_t off = swoff(r, u);
        *reinterpret_cast<uint4*>(outHi + off) = make_uint4(hw_[0], hw_[1], hw_[2], hw_[3]);
        *reinterpret_cast<uint4*>(outLo + off) = make_uint4(lw_[0], lw_[1], lw_[2], lw_[3]);
    }
}

// ---------------------------------------------------------------------------
// prep B: codebook -> fp16 hi/lo PRE-SWIZZLED tiles. grid (8 nc, 8 stage)
// ---------------------------------------------------------------------------
__global__ __launch_bounds__(256) void prep_b(const float* __restrict__ cb) {
    const int nc = blockIdx.x, stage = blockIdx.y;
    unsigned char* outHi = gB + ((size_t)(nc * 2 + 0) * 8 + stage) * 8192;
    unsigned char* outLo = gB + ((size_t)(nc * 2 + 1) * 8 + stage) * 8192;
    #pragma unroll
    for (int v = 0; v < 2; v++) {
        int id = v * 256 + threadIdx.x;
        int r = id >> 2, u = id & 3;
        const float* src = cb + (size_t)(nc * 128 + r) * Dc + stage * 32 + u * 8;
        uint32_t hw_[4], lw_[4];
        #pragma unroll
        for (int p = 0; p < 4; p++) {
            float v0 = src[2*p], v1 = src[2*p + 1];
            __half h0 = __float2half_rn(v0), h1 = __float2half_rn(v1);
            float l0 = v0 - __half2float(h0), l1 = v1 - __half2float(h1);
            hw_[p] = (uint32_t)__half_as_ushort(h0) | ((uint32_t)__half_as_ushort(h1) << 16);
            lw_[p] = pkh(l0, l1);
        }
        uint32_t off = swoff(r, u);
        *reinterpret_cast<uint4*>(outHi + off) = make_uint4(hw_[0], hw_[1], hw_[2], hw_[3]);
        *reinterpret_cast<uint4*>(outLo + off) = make_uint4(lw_[0], lw_[1], lw_[2], lw_[3]);
    }
}

// ---------------------------------------------------------------------------
__global__ void cnorm_kernel(const float* __restrict__ cb) {
    int warp = (blockIdx.x * blockDim.x + threadIdx.x) >> 5;
    int lane = threadIdx.x & 31;
    if (warp >= Kc) return;
    const float* row = cb + warp * Dc;
    float s = 0.f;
    #pragma unroll
    for (int d = lane; d < Dc; d += 32) { float v = row[d]; s = fmaf(v, v, s); }
    #pragma unroll
    for (int o = 16; o; o >>= 1) s += __shfl_xor_sync(0xFFFFFFFFu, s, o);
    if (lane == 0) g_cnorm[warp] = s;
}

// ---------------------------------------------------------------------------
// argmin via mma.sync: 8 compute warps (2x4 grid, 64x32 tiles) + 1 producer
// warp. B stages flow through a 4-deep mbarrier ring fed by cp.async.bulk.
// NO block barrier inside the 64-stage loop: consumer warps drift freely,
// decorrelating ldsm bursts from MMA bursts across warps.
// ---------------------------------------------------------------------------
__global__ __launch_bounds__(NTHR, 1) void argmin_mma() {
    extern __shared__ __align__(128) unsigned char smem[];
    const uint32_t sb = smem_u32(smem);
    const int tid = threadIdx.x, lane = tid & 31, wid = tid >> 5;
    const int bm = blockIdx.x;

    const uint32_t MB_FULL  = sb + SM_MB;        // full[b]  = +b*8
    const uint32_t MB_EMPTY = sb + SM_MB + 32;   // empty[b] = +b*8

    float* sm_cn = reinterpret_cast<float*>(smem + SM_CN);
    unsigned long long* sBest = reinterpret_cast<unsigned long long*>(smem + SM_BEST);

    if (tid == 0) {
        #pragma unroll
        for (int b = 0; b < 4; b++) {
            MBAR_INIT(MB_FULL + b * 8, 1);    // tx-based completion
            MBAR_INIT(MB_EMPTY + b * 8, 8);   // one arrive per compute warp
        }
    }
    for (int i = tid; i < Kc; i += NTHR) sm_cn[i] = g_cnorm[i];
    if (tid < 128) sBest[tid] = ~0ull;

    // A image -> smem: plain linear copy (image pre-swizzled)
    {
        const unsigned char* src = gA + (size_t)bm * 131072;
        for (int i = tid; i < 8192; i += NTHR)
            cp16(sb + SM_A + i * 16, src + (size_t)i * 16);
        cp_commit();
        cp_wait0();
    }
    __syncthreads();   // A ready + mbarriers initialized, visible to all

    if (wid == 8) {
        // ---------------- producer warp ----------------
        if (lane == 0) {
            int ep[4] = {0, 0, 0, 0};
            #pragma unroll 1
            for (int u = 0; u < TSTAGE; u++) {
                const int b = u & 3;
                if (u >= 4) { mbar_wait(MB_EMPTY + b * 8, ep[b]); ep[b] ^= 1; }
                const int nc = u >> 3, s = u & 7;
                const uint32_t buf = sb + SM_B + b * 16384;
                MBAR_EXPECT(MB_FULL + b * 8, 16384u);
                bulk_copy(buf,        gB + ((size_t)(nc * 2 + 0) * 8 + s) * 8192, 8192u, MB_FULL + b * 8);
                bulk_copy(buf + 8192, gB + ((size_t)(nc * 2 + 1) * 8 + s) * 8192, 8192u, MB_FULL + b * 8);
            }
        }
    } else {
        // ---------------- compute warps ----------------
        const int wm = wid & 1, wn = wid >> 1;
        const int a_r = wm * 64 + (lane & 15);                       // + mi*16
        const int a_u = lane >> 4;                                   // + kk*2
        const int b_r = wn * 32 + (lane & 7) + ((lane >> 4) << 3);   // + np*16
        const int b_u = (lane >> 3) & 1;                             // + kk*2

        float best8[8];
        int   bid8[8];
        #pragma unroll
        for (int i = 0; i < 8; i++) { best8[i] = 3.4e38f; bid8[i] = 0; }

        float acc[4][4][4];
        #pragma unroll
        for (int mi = 0; mi < 4; mi++)
            #pragma unroll
            for (int ni = 0; ni < 4; ni++)
                #pragma unroll
                for (int c = 0; c < 4; c++) acc[mi][ni][c] = 0.f;

        int fp = 0;  // full-phase parity (all 4 bufs cycle together, flip every 4 stages)

        #pragma unroll 1
        for (int t = 0; t < TSTAGE; t++) {
            const int b = t & 3;
            const int s = t & 7;
            mbar_wait(MB_FULL + b * 8, fp);
            if (b == 3) fp ^= 1;

            const uint32_t bufhi = sb + SM_B + b * 16384;
            const uint32_t buflo = bufhi + 8192;
            const uint32_t SAhi  = sb + SM_A + s * 8192;
            const uint32_t SAlo  = SAhi + 65536;

            // load ALL B fragments for this stage (both kk), then release buffer
            uint32_t bh0[8], bl0[8], bh1[8], bl1[8];
            #pragma unroll
            for (int np = 0; np < 2; np++) {
                int r = b_r + np * 16;
                uint32_t o0 = swoff(r, 0 * 2 + b_u);
                uint32_t o1 = swoff(r, 1 * 2 + b_u);
                ldsm4(bh0[np*4+0], bh0[np*4+1], bh0[np*4+2], bh0[np*4+3], bufhi + o0);
                ldsm4(bl0[np*4+0], bl0[np*4+1], bl0[np*4+2], bl0[np*4+3], buflo + o0);
                ldsm4(bh1[np*4+0], bh1[np*4+1], bh1[np*4+2], bh1[np*4+3], bufhi + o1);
                ldsm4(bl1[np*4+0], bl1[np*4+1], bl1[np*4+2], bl1[np*4+3], buflo + o1);
            }
            if (lane == 0) MBAR_ARRIVE(MB_EMPTY + b * 8);

            #pragma unroll
            for (int kk = 0; kk < 2; kk++) {
                const uint32_t* bh = kk ? bh1 : bh0;
                const uint32_t* bl = kk ? bl1 : bl0;
                uint32_t ah[16], al[16];
                #pragma unroll
                for (int mi = 0; mi < 4; mi++) {
                    int r = a_r + mi * 16;
                    uint32_t off = swoff(r, kk * 2 + a_u);
                    ldsm4(ah[mi*4+0], ah[mi*4+1], ah[mi*4+2], ah[mi*4+3], SAhi + off);
                    ldsm4(al[mi*4+0], al[mi*4+1], al[mi*4+2], al[mi*4+3], SAlo + off);
                }
                // pass 1: A-hi * B-hi
                #pragma unroll
                for (int mi = 0; mi < 4; mi++)
                    #pragma unroll
                    for (int ni = 0; ni < 4; ni++)
                        mma16816(acc[mi][ni][0], acc[mi][ni][1], acc[mi][ni][2], acc[mi][ni][3],
                                 ah[mi*4+0], ah[mi*4+1], ah[mi*4+2], ah[mi*4+3],
                                 bh[(ni>>1)*4 + (ni&1)*2], bh[(ni>>1)*4 + (ni&1)*2 + 1]);
                // pass 2: A-lo * B-hi
                #pragma unroll
                for (int mi = 0; mi < 4; mi++)
                    #pragma unroll
                    for (int ni = 0; ni < 4; ni++)
                        mma16816(acc[mi][ni][0], acc[mi][ni][1], acc[mi][ni][2], acc[mi][ni][3],
                                 al[mi*4+0], al[mi*4+1], al[mi*4+2], al[mi*4+3],
                                 bh[(ni>>1)*4 + (ni&1)*2], bh[(ni>>1)*4 + (ni&1)*2 + 1]);
                // pass 3: A-hi * B-lo
                #pragma unroll
                for (int mi = 0; mi < 4; mi++)
                    #pragma unroll
                    for (int ni = 0; ni < 4; ni++)
                        mma16816(acc[mi][ni][0], acc[mi][ni][1], acc[mi][ni][2], acc[mi][ni][3],
                                 ah[mi*4+0], ah[mi*4+1], ah[mi*4+2], ah[mi*4+3],
                                 bl[(ni>>1)*4 + (ni&1)*2], bl[(ni>>1)*4 + (ni&1)*2 + 1]);
            }

            if (s == 7) {
                const int nc = t >> 3;
                #pragma unroll
                for (int mi = 0; mi < 4; mi++)
                    #pragma unroll
                    for (int ni = 0; ni < 4; ni++)
                        #pragma unroll
                        for (int c = 0; c < 4; c++) {
                            int code = nc * 128 + wn * 32 + ni * 8 + (lane & 3) * 2 + (c & 1);
                            float score = fmaf(-2.f, acc[mi][ni][c], sm_cn[code]);
                            int slot = mi * 2 + (c >> 1);
                            if (score < best8[slot]) { best8[slot] = score; bid8[slot] = code; }
                            acc[mi][ni][c] = 0.f;
                        }
            }
        }

        #pragma unroll
        for (int slot = 0; slot < 8; slot++) {
            int row = wm * 64 + (slot >> 1) * 16 + (lane >> 2) + 8 * (slot & 1);
            unsigned long long pack =
                ((unsigned long long)fkey(best8[slot]) << 32) | (unsigned int)bid8[slot];
            atomicMin(&sBest[row], pack);
        }
    }

    __syncthreads();
    if (tid < 128)
        g_idx[bm * M_TILE + tid] = (int)(unsigned int)(sBest[tid] & 0xFFFFFFFFull);
}

// ---------------------------------------------------------------------------
__global__ void output_kernel(const float* __restrict__ x,
                              const float* __restrict__ cb,
                              float* __restrict__ zhat,
                              float* __restrict__ zq)
{
    int t = blockIdx.x * blockDim.x + threadIdx.x;
    if (t >= NELEM / 4) return;
    int n  = t >> 6;
    int d4 = t & 63;
    int k  = g_idx[n];
    float4 c  = *reinterpret_cast<const float4*>(cb + (size_t)k * Dc + d4 * 4);
    float4 xv = *reinterpret_cast<const float4*>(x + (size_t)t * 4);
    float4 zh;
    zh.x = xv.x + (c.x - xv.x);
    zh.y = xv.y + (c.y - xv.y);
    zh.z = xv.z + (c.z - xv.z);
    zh.w = xv.w + (c.w - xv.w);
    *reinterpret_cast<float4*>(zq   + (size_t)t * 4) = c;
    *reinterpret_cast<float4*>(zhat + (size_t)t * 4) = zh;
}

// ---------------------------------------------------------------------------
extern "C" void kernel_launch(void* const* d_in, const int* in_sizes, int n_in,
                              void* d_out, int out_size)
{
    const float* x  = (const float*)d_in[0];
    const float* cb = (const float*)d_in[1];
    float* zhat = (float*)d_out;
    float* zq   = (float*)d_out + NELEM;

    static int attr_set = 0;
    if (!attr_set) {
        cudaFuncSetAttribute(argmin_mma, cudaFuncAttributeMaxDynamicSharedMemorySize, SM_TOTAL);
        attr_set = 1;
    }

    prep_a<<<dim3(NBLK, NSTG), 256>>>(x);
    prep_b<<<dim3(8, NSTG), 256>>>(cb);
    cnorm_kernel<<<Kc / 8, 256>>>(cb);
    argmin_mma<<<NBLK, NTHR, SM_TOTAL>>>();
    output_kernel<<<(NELEM / 4 + 255) / 256, 256>>>(x, cb, zhat, zq);
}